// round 17
// baseline (speedup 1.0000x reference)
#include <cuda_runtime.h>
#include <cstdint>
#include <cstddef>

// ---------------------------------------------------------------------------
// graph12 — Round 17: kFuse warp specialization — warps 6-7 own ALL batch
//   stats/bisum/uni (from smem-staged x), overlapping GEMM2 on warps 0-5.
//   (k_projA, k6, k7 unchanged from R16 @ 698 µs.)
// ---------------------------------------------------------------------------

#define NB    16384
#define ND    1024
#define NR3   (NB*3)

__device__ float g_W1t  [128*1024];          // W1r transposed [n][k], tf32
__device__ float g_W2t  [1024*64];           // W2 transposed [n][k], tf32
__device__ float g_l1Wp [3072*64];           // tf32, padded 50->64
__device__ float g_bnsc [3072];
__device__ float g_PQ1  [(size_t)NR3*128];
__device__ float g_act2 [(size_t)6*NB*64];
__device__ float g_uni  [(size_t)NB*ND];
__device__ float g_bisum[(size_t)NB*ND];
__device__ float g_tri  [(size_t)NB*ND];
__device__ float g_wuni [NB*3];
__device__ float g_wbi  [NB*3];
__device__ float g_sbi  [NB*3];
__device__ float g_wtri [NB*6];

// -------------------------- helpers -----------------------------------------
__device__ __forceinline__ float f2tf_f(float f) {
    unsigned r;
    asm("cvt.rna.tf32.f32 %0, %1;" : "=r"(r) : "f"(f));
    return __uint_as_float(r);
}

__device__ __forceinline__ float tanh_fast(float x) {
    float r;
    asm("tanh.approx.f32 %0, %1;" : "=f"(r) : "f"(x));
    return r;
}

// exp(v) for v in [-0.02, 1.01]: degree-7 Taylor (Horner), rel err <= ~7e-5.
__device__ __forceinline__ float exp_poly(float v) {
    float p = 1.984127e-4f;
    p = fmaf(p, v, 1.3888889e-3f);
    p = fmaf(p, v, 8.3333333e-3f);
    p = fmaf(p, v, 4.1666667e-2f);
    p = fmaf(p, v, 1.6666667e-1f);
    p = fmaf(p, v, 0.5f);
    p = fmaf(p, v, 1.0f);
    p = fmaf(p, v, 1.0f);
    return p;
}

__device__ __forceinline__ void mma_t(float4& d, unsigned a0, unsigned a1,
                                      unsigned a2, unsigned a3,
                                      unsigned b0, unsigned b1) {
    asm volatile(
        "mma.sync.aligned.m16n8k8.row.col.f32.tf32.tf32.f32 "
        "{%0,%1,%2,%3}, {%4,%5,%6,%7}, {%8,%9}, {%0,%1,%2,%3};"
        : "+f"(d.x), "+f"(d.y), "+f"(d.z), "+f"(d.w)
        : "r"(a0), "r"(a1), "r"(a2), "r"(a3), "r"(b0), "r"(b1));
}

__device__ __forceinline__ uint4 ldsm4(unsigned addr) {
    uint4 r;
    asm volatile("ldmatrix.sync.aligned.m8n8.x4.shared.b16 {%0,%1,%2,%3}, [%4];"
                 : "=r"(r.x), "=r"(r.y), "=r"(r.z), "=r"(r.w) : "r"(addr));
    return r;
}

__device__ __forceinline__ unsigned a_ptr(unsigned base, int rbase, int S, int lane) {
    return base + ((rbase + (lane & 15))*S + ((lane & 16) >> 2))*4;
}
__device__ __forceinline__ unsigned b_ptr(unsigned base, int nbase, int St, int lane) {
    return base + ((nbase + (lane & 7) + ((lane & 16) >> 1))*St + ((lane & 8) >> 1))*4;
}

__device__ __forceinline__ void cpasync16(float* dst_smem, const float* src) {
    unsigned d = (unsigned)__cvta_generic_to_shared(dst_smem);
    asm volatile("cp.async.cg.shared.global [%0], [%1], 16;" :: "r"(d), "l"(src));
}
#define CP_COMMIT  asm volatile("cp.async.commit_group;")
#define CP_WAIT0   asm volatile("cp.async.wait_group 0;")
#define CP_WAIT1   asm volatile("cp.async.wait_group 1;")

// -------------------------- k0: prep ----------------------------------------
__global__ void k0_prep(const float* __restrict__ W1, const float* __restrict__ W2,
                        const float* __restrict__ l1W, const float* __restrict__ bng)
{
    int i = blockIdx.x * 256 + threadIdx.x;
    if (i < 131072) {
        int n = i >> 10, k = i & 1023;
        float v = (n < 64) ? W1[(size_t)k*64 + n] : W1[(size_t)(1024 + k)*64 + (n - 64)];
        g_W1t[i] = f2tf_f(v);
    } else if (i < 196608) {
        int i2 = i - 131072;
        int n = i2 >> 6, k = i2 & 63;
        g_W2t[i2] = f2tf_f(W2[(size_t)k*1024 + n]);
    } else if (i < 393216) {
        int i3 = i - 196608;
        int row = i3 >> 6, c = i3 & 63;
        g_l1Wp[i3] = (c < 50) ? f2tf_f(l1W[(size_t)row*50 + c]) : 0.f;
    } else if (i < 396288) {
        int j = i - 393216;
        float mult = (j < 1024) ? 1.f : ((j < 2048) ? (1.f/3.f) : (1.f/6.f));
        g_bnsc[j] = bng[j] * rsqrtf(1.0f + 1e-5f) * mult;
    }
}

// -------------------------- kP: PQ1 projection + attention stats ------------
#define KPA_STAGE (96*36 + 128*36)            // 8064 floats
#define KPA_SMEM  ((3*KPA_STAGE + 1024)*4)

__device__ __forceinline__ void kpa_issue(const float* __restrict__ x, size_t m0,
                                          float* stage, int t, int tid)
{
    float* As  = stage;                 // [96][36]  raw x
    float* Bts = stage + 96*36;         // [128][36] W1t chunk
    int kk = t * 32;
#pragma unroll
    for (int j = 0; j < 3; j++) {
        int i = tid + j*256;
        int r = i >> 3, kq = i & 7;
        cpasync16(&As[r*36 + kq*4], &x[(m0 + r)*1024 + kk + kq*4]);
    }
#pragma unroll
    for (int j = 0; j < 4; j++) {
        int i = tid + j*256;
        int n = i >> 3, kq = i & 7;
        cpasync16(&Bts[n*36 + kq*4], &g_W1t[(size_t)n*1024 + kk + kq*4]);
    }
    CP_COMMIT;
}

__global__ __launch_bounds__(256) void k_projA(
    const float* __restrict__ x, const float* __restrict__ attW,
    const float* __restrict__ attb, float* __restrict__ outW, int wflag)
{
    extern __shared__ float smp[];
    float* attWs = smp + 3*KPA_STAGE;
    int tid = threadIdx.x;
    int bid = blockIdx.x;
    size_t m0 = (size_t)bid * 96;
    int bb0 = bid * 32;
    int lane = tid & 31, wid = tid >> 5;
    int t4 = lane & 3, g = lane >> 2;

    for (int i = tid; i < 1024; i += 256) attWs[i] = attW[i];

    float4 acc[2][8] = {};              // MMA warps
    float sAtt[3] = {}, sE[3] = {}, sPP[3] = {};   // stat warps

    kpa_issue(x, m0, smp,             0, tid);
    kpa_issue(x, m0, smp + KPA_STAGE, 1, tid);

    int s = 0;
    for (int t = 0; t < 32; t++) {
        if (t < 31) { CP_WAIT1; } else { CP_WAIT0; }
        __syncthreads();
        if (t + 2 < 32)
            kpa_issue(x, m0, smp + ((s + 2) % 3)*KPA_STAGE, t + 2, tid);
        float* Ac = smp + s*KPA_STAGE;
        if (wid < 6) {
            int wm = wid >> 1, wn = wid & 1;
            unsigned Au = (unsigned)__cvta_generic_to_shared(Ac);
            unsigned Bu = Au + 96*36*4;
            unsigned pA0 = a_ptr(Au, wm*32, 36, lane);
            unsigned pA1 = pA0 + 16*36*4;
            unsigned pB  = b_ptr(Bu, wn*64, 36, lane);
#pragma unroll
            for (int ks = 0; ks < 4; ks++) {
                uint4 a0 = ldsm4(pA0 + ks*32);
                uint4 a1 = ldsm4(pA1 + ks*32);
                uint4 bv[4];
#pragma unroll
                for (int p = 0; p < 4; p++) bv[p] = ldsm4(pB + p*16*36*4 + ks*32);
#pragma unroll
                for (int n = 0; n < 8; n++) {
                    unsigned b0 = (n & 1) ? bv[n>>1].z : bv[n>>1].x;
                    unsigned b1 = (n & 1) ? bv[n>>1].w : bv[n>>1].y;
                    mma_t(acc[0][n], a0.x, a0.y, a0.z, a0.w, b0, b1);
                    mma_t(acc[1][n], a1.x, a1.y, a1.z, a1.w, b0, b1);
                }
            }
        } else {
            int st = tid - 192;
            int b = st >> 1, half = st & 1;
            const float* Ar = Ac + (3*b)*36 + half*16;
            const float* ws = attWs + t*32 + half*16;
#pragma unroll
            for (int c = 0; c < 16; c++) {
                float xa = Ar[c], xv = Ar[36 + c], xl = Ar[72 + c];
                float w = ws[c];
                sAtt[0] = fmaf(xa, w, sAtt[0]);
                sAtt[1] = fmaf(xv, w, sAtt[1]);
                sAtt[2] = fmaf(xl, w, sAtt[2]);
                float e0 = __expf(xa), e1 = __expf(xv), e2 = __expf(xl);
                sE[0] += e0; sE[1] += e1; sE[2] += e2;
                sPP[0] = fmaf(e0, e1, sPP[0]);
                sPP[1] = fmaf(e0, e2, sPP[1]);
                sPP[2] = fmaf(e1, e2, sPP[2]);
            }
        }
        s = (s + 1) % 3;
    }

    if (wid < 6) {
        int wm = wid >> 1, wn = wid & 1;
#pragma unroll
        for (int m = 0; m < 2; m++) {
            size_t r0 = m0 + wm*32 + m*16 + g;
            size_t r1 = r0 + 8;
#pragma unroll
            for (int n = 0; n < 8; n++) {
                int col = wn*64 + n*8 + t4*2;
                float2 o0; o0.x = acc[m][n].x; o0.y = acc[m][n].y;
                float2 o1; o1.x = acc[m][n].z; o1.y = acc[m][n].w;
                *(float2*)&g_PQ1[r0*128 + col] = o0;
                *(float2*)&g_PQ1[r1*128 + col] = o1;
            }
        }
    } else {
#pragma unroll
        for (int m = 0; m < 3; m++) {
            sAtt[m] += __shfl_xor_sync(0xffffffffu, sAtt[m], 1);
            sE[m]   += __shfl_xor_sync(0xffffffffu, sE[m],   1);
            sPP[m]  += __shfl_xor_sync(0xffffffffu, sPP[m],  1);
        }
        int st = tid - 192;
        int b = st >> 1, half = st & 1;
        if (half == 0) {
            int gb = bb0 + b;
            float ab = attb[0];
            float t0 = tanhf(sAtt[0] + ab), t1 = tanhf(sAtt[1] + ab), t2 = tanhf(sAtt[2] + ab);
            float mm = fmaxf(t0, fmaxf(t1, t2));
            float e0 = expf(t0 - mm), e1 = expf(t1 - mm), e2 = expf(t2 - mm);
            float inv = 1.f / (e0 + e1 + e2);
            float sa = e0*inv, sv = e1*inv, sl = e2*inv;
            float dav = sPP[0] / (sE[0]*sE[1]);
            float dal = sPP[1] / (sE[0]*sE[2]);
            float dvl = sPP[2] / (sE[1]*sE[2]);
            float sav = (sa + sv) / (dav + 0.5f);
            float sal = (sa + sl) / (dal + 0.5f);
            float svl = (sl + sv) / (dvl + 0.5f);
            g_wuni[gb*3+0] = sa; g_wuni[gb*3+1] = sv; g_wuni[gb*3+2] = sl;
            g_sbi [gb*3+0] = sav; g_sbi[gb*3+1] = sal; g_sbi[gb*3+2] = svl;
            float m3 = fmaxf(sav, fmaxf(sal, svl));
            float f0 = expf(sav - m3), f1 = expf(sal - m3), f2 = expf(svl - m3);
            float fi = 1.f / (f0 + f1 + f2);
            g_wbi[gb*3+0] = f0*fi; g_wbi[gb*3+1] = f1*fi; g_wbi[gb*3+2] = f2*fi;
            if (wflag) {
                float* o = outW + (size_t)gb*12;
                o[0] = sa; o[1] = sv; o[2] = sl;
                o[3] = f0*fi; o[4] = f1*fi; o[5] = f2*fi;
            }
        }
    }
}

// -------------------------- kFuse: stage-2 megafusion (warp-specialized) ----
#define KF_PQ1   0            // [48][132] = 6336
#define KF_ACT1  6336         // [48][68]  = 3264
#define KF_BI3   9600         // [48][68]  = 3264
#define KF_W2    12864        // [64][68]  = 4352
#define KF_W1    17216        // [128][68] = 8704 (reused PQ2s [48][136])
#define KF_XS    25920        // [48][68]  = 3264
#define KF_B1    29184        // 64
#define KF_WBI   29248        // 48
#define KF_TOTF  (29248+48+16)
#define KF_SMEM  (KF_TOTF*4)

__global__ __launch_bounds__(256) void kFuse(
    const float* __restrict__ x, const float* __restrict__ b1,
    const float* __restrict__ b2, float* __restrict__ outW, int wflag)
{
    extern __shared__ float sf[];
    float* PQ1s = sf + KF_PQ1;
    float* act1s= sf + KF_ACT1;
    float* bi3c = sf + KF_BI3;
    float* W2ts = sf + KF_W2;
    float* W1ts = sf + KF_W1;
    float* xs   = sf + KF_XS;
    float* b1s  = sf + KF_B1;
    float* wbis = sf + KF_WBI;

    int tid = threadIdx.x;
    int bb0 = blockIdx.x * 16;
    int lane = tid & 31, wid = tid >> 5;
    int t4 = lane & 3, g = lane >> 2;
    int wm = wid >> 1, wn = wid & 1;

    for (int i = tid; i < 1536; i += 256) {
        int r = i >> 5, c4 = i & 31;
        int p = r >> 4, b = r & 15;
        cpasync16(&PQ1s[r*132 + c4*4], &g_PQ1[((size_t)(bb0 + b)*3 + p)*128 + c4*4]);
    }
    CP_COMMIT;
    if (tid < 64) b1s[tid] = b1[tid];
    if (tid < 48) { int p = tid >> 4, b = tid & 15; wbis[tid] = g_wbi[(bb0 + b)*3 + p]; }

    // stat-thread setup: 1 batch per thread quad (warps 6-7)
    int st = tid - 192;                  // valid when wid >= 6
    int sb = st >> 2;                    // batch 0..15
    int sq = st & 3;                     // quarter
    float su0 = 0.f, su1 = 0.f, su2 = 0.f;
    if (wid >= 6) {
        su0 = g_wuni[(size_t)(bb0 + sb)*3 + 0];
        su1 = g_wuni[(size_t)(bb0 + sb)*3 + 1];
        su2 = g_wuni[(size_t)(bb0 + sb)*3 + 2];
    }
    CP_WAIT0;
    __syncthreads();
    for (int i = tid; i < 3072; i += 256) {
        int r = i >> 6, k = i & 63;
        int p = r >> 4, b = r & 15;
        int f = (p == 2) ? 1 : 0;
        int s = (p == 0) ? 1 : 2;
        float tv = PQ1s[(f*16+b)*132 + k] + PQ1s[(s*16+b)*132 + 64 + k] + b1s[k];
        act1s[r*68 + k] = tv > 0.f ? tv : 0.2f*tv;
    }
    __syncthreads();

    unsigned act1u = (unsigned)__cvta_generic_to_shared(act1s);
    unsigned bi3u  = (unsigned)__cvta_generic_to_shared(bi3c);
    unsigned w2tu  = (unsigned)__cvta_generic_to_shared(W2ts);
    unsigned w1tu  = (unsigned)__cvta_generic_to_shared(W1ts);
    unsigned pA1 = a_ptr(act1u, wm*16, 68, lane);
    unsigned pA2 = a_ptr(bi3u,  wm*16, 68, lane);
    unsigned pB1 = b_ptr(w2tu, wn*32, 68, lane);
    unsigned pB2 = b_ptr(w1tu, wn*64, 68, lane);

    float aE[3] = {}, aX[3] = {}, aP[3] = {}, aQ[3] = {};
    float4 pq2[8] = {};

    for (int n = 0; n < 16; n++) {
        int n0 = n * 64;
        // group 1: W2t chunk + x chunk (needed for GEMM1 / stats)
        for (int i = tid; i < 1024; i += 256) {
            int r = i >> 4, c4 = i & 15;
            cpasync16(&W2ts[r*68 + c4*4], &g_W2t[(size_t)(n0 + r)*64 + c4*4]);
        }
        for (int i = tid; i < 768; i += 256) {
            int r = i >> 4, c4 = i & 15;          // row r = p*16+b
            int p = r >> 4, b = r & 15;
            cpasync16(&xs[r*68 + c4*4],
                      &x[((size_t)(bb0 + b)*3 + p)*1024 + n0 + c4*4]);
        }
        CP_COMMIT;
        // group 2: W1t chunk (needed only for GEMM2)
        for (int i = tid; i < 2048; i += 256) {
            int r = i >> 4, c4 = i & 15;
            cpasync16(&W1ts[r*68 + c4*4], &g_W1t[(size_t)r*1024 + n0 + c4*4]);
        }
        CP_COMMIT;
        CP_WAIT1;          // W2t + xs arrived; W1t may still be in flight
        __syncthreads();

        // GEMM1: act1 @ W2 chunk -> bi3c (tanh.approx * wbi, lrelu)
        if (wid < 6) {
            float4 acc[4] = {};
#pragma unroll
            for (int ks = 0; ks < 8; ks++) {
                uint4 a  = ldsm4(pA1 + ks*32);
                uint4 b0 = ldsm4(pB1 + ks*32);
                uint4 b1v= ldsm4(pB1 + 16*68*4 + ks*32);
                mma_t(acc[0], a.x,a.y,a.z,a.w, b0.x, b0.y);
                mma_t(acc[1], a.x,a.y,a.z,a.w, b0.z, b0.w);
                mma_t(acc[2], a.x,a.y,a.z,a.w, b1v.x, b1v.y);
                mma_t(acc[3], a.x,a.y,a.z,a.w, b1v.z, b1v.w);
            }
            int r0 = wm*16 + g, r1 = r0 + 8;
            float w0 = wbis[r0], w1 = wbis[r1];
#pragma unroll
            for (int q = 0; q < 4; q++) {
                int col = wn*32 + q*8 + t4*2;
                float2 b2v = *(const float2*)&b2[n0 + col];
                float t, v;
                t = tanh_fast(acc[q].x + b2v.x)*w0; v = t > 0.f ? t : 0.01f*t; bi3c[r0*68 + col]   = v;
                t = tanh_fast(acc[q].y + b2v.y)*w0; v = t > 0.f ? t : 0.01f*t; bi3c[r0*68 + col+1] = v;
                t = tanh_fast(acc[q].z + b2v.x)*w1; v = t > 0.f ? t : 0.01f*t; bi3c[r1*68 + col]   = v;
                t = tanh_fast(acc[q].w + b2v.y)*w1; v = t > 0.f ? t : 0.01f*t; bi3c[r1*68 + col+1] = v;
            }
        }
        CP_WAIT0;          // ALL threads drain W1t before the barrier (issuer-side wait)
        __syncthreads();   // bi3c + W1ts visible

        if (wid < 6) {
            // GEMM2 (concurrent with stat warps below)
#pragma unroll
            for (int ks = 0; ks < 8; ks++) {
                uint4 a = ldsm4(pA2 + ks*32);
                uint4 bv[4];
#pragma unroll
                for (int p = 0; p < 4; p++) bv[p] = ldsm4(pB2 + p*16*68*4 + ks*32);
#pragma unroll
                for (int q = 0; q < 8; q++) {
                    unsigned b0 = (q & 1) ? bv[q>>1].z : bv[q>>1].x;
                    unsigned b1 = (q & 1) ? bv[q>>1].w : bv[q>>1].y;
                    mma_t(pq2[q], a.x,a.y,a.z,a.w, b0, b1);
                }
            }
        } else {
            // stats + bisum + unimodal for this thread's batch quarter
            float* bsrow = &g_bisum[(size_t)(bb0 + sb)*1024 + n0];
            float* unrow = &g_uni  [(size_t)(bb0 + sb)*1024 + n0];
#pragma unroll
            for (int u = 0; u < 4; u++) {
                int c = sq*16 + u*4;
                float4 v0 = *(float4*)&bi3c[sb*68 + c];
                float4 v1 = *(float4*)&bi3c[(16+sb)*68 + c];
                float4 v2 = *(float4*)&bi3c[(32+sb)*68 + c];
                float4 xa4 = *(float4*)&xs[(0*16+sb)*68 + c];
                float4 xv4 = *(float4*)&xs[(1*16+sb)*68 + c];
                float4 xl4 = *(float4*)&xs[(2*16+sb)*68 + c];
                float4 bs, un;
                bs.x = v0.x+v1.x+v2.x; bs.y = v0.y+v1.y+v2.y;
                bs.z = v0.z+v1.z+v2.z; bs.w = v0.w+v1.w+v2.w;
                un.x = (su0*xa4.x + su1*xv4.x + su2*xl4.x)*(1.0f/3.0f);
                un.y = (su0*xa4.y + su1*xv4.y + su2*xl4.y)*(1.0f/3.0f);
                un.z = (su0*xa4.z + su1*xv4.z + su2*xl4.z)*(1.0f/3.0f);
                un.w = (su0*xa4.w + su1*xv4.w + su2*xl4.w)*(1.0f/3.0f);
                *(float4*)&bsrow[c] = bs;
                *(float4*)&unrow[c] = un;
                const float* v0p = &v0.x; const float* v1p = &v1.x; const float* v2p = &v2.x;
                const float* xap = &xa4.x; const float* xvp = &xv4.x; const float* xlp = &xl4.x;
#pragma unroll
                for (int e = 0; e < 4; e++) {
                    float e0 = exp_poly(v0p[e]);
                    float e1 = exp_poly(v1p[e]);
                    float e2 = exp_poly(v2p[e]);
                    float xa = __expf(xap[e]);
                    float xv = __expf(xvp[e]);
                    float xl = __expf(xlp[e]);
                    aE[0] += e0; aE[1] += e1; aE[2] += e2;
                    aX[0] += xa; aX[1] += xv; aX[2] += xl;
                    aP[0] = fmaf(e0, e2, aP[0]);
                    aP[1] = fmaf(e0, e1, aP[1]);
                    aP[2] = fmaf(e1, e2, aP[2]);
                    aQ[0] = fmaf(e0, xl, aQ[0]);
                    aQ[1] = fmaf(e1, xv, aQ[1]);
                    aQ[2] = fmaf(e2, xa, aQ[2]);
                }
            }
        }
        __syncthreads();
    }

    // ---- stats reduce -> w_tri (stat warps only; quad reduce) ----
    if (wid >= 6) {
#pragma unroll
        for (int v = 0; v < 3; v++) {
            aE[v] += __shfl_xor_sync(0xffffffffu, aE[v], 1);
            aE[v] += __shfl_xor_sync(0xffffffffu, aE[v], 2);
            aX[v] += __shfl_xor_sync(0xffffffffu, aX[v], 1);
            aX[v] += __shfl_xor_sync(0xffffffffu, aX[v], 2);
            aP[v] += __shfl_xor_sync(0xffffffffu, aP[v], 1);
            aP[v] += __shfl_xor_sync(0xffffffffu, aP[v], 2);
            aQ[v] += __shfl_xor_sync(0xffffffffu, aQ[v], 1);
            aQ[v] += __shfl_xor_sync(0xffffffffu, aQ[v], 2);
        }
        if (sq == 0) {
            int b = bb0 + sb;
            float d0 = aP[0] / (aE[0]*aE[2]);
            float d1 = aP[1] / (aE[0]*aE[1]);
            float d2 = aP[2] / (aE[1]*aE[2]);
            float d3 = aQ[0] / (aE[0]*aX[2]);
            float d4 = aQ[1] / (aE[1]*aX[1]);
            float d5 = aQ[2] / (aE[2]*aX[0]);
            float sa = g_wuni[b*3+0], sv = g_wuni[b*3+1], sl = g_wuni[b*3+2];
            float sav = g_sbi[b*3+0], sal = g_sbi[b*3+1], svl = g_sbi[b*3+2];
            float nn[6];
            nn[0] = (sav + svl)/(d0 + 0.5f);
            nn[1] = (sav + sal)/(d1 + 0.5f);
            nn[2] = (sal + svl)/(d2 + 0.5f);
            nn[3] = (sav + sl )/(d3 + 0.5f);
            nn[4] = (sal + sv )/(d4 + 0.5f);
            nn[5] = (sa  + svl)/(d5 + 0.5f);
            float m = nn[0];
#pragma unroll
            for (int k = 1; k < 6; k++) m = fmaxf(m, nn[k]);
            float e[6], ss = 0.f;
#pragma unroll
            for (int k = 0; k < 6; k++) { e[k] = expf(nn[k]-m); ss += e[k]; }
            float inv = 1.f/ss;
#pragma unroll
            for (int k = 0; k < 6; k++) {
                g_wtri[(size_t)b*6 + k] = e[k]*inv;
                if (wflag) outW[(size_t)b*12 + 6 + k] = e[k]*inv;
            }
        }
    }

    // ---- PQ2 -> smem (reuse W1ts region as [48][136]) ----
    __syncthreads();
    if (wid < 6) {
        int r0 = wm*16 + g, r1 = r0 + 8;
#pragma unroll
        for (int q = 0; q < 8; q++) {
            int col = wn*64 + q*8 + t4*2;
            W1ts[r0*136 + col]   = pq2[q].x;
            W1ts[r0*136 + col+1] = pq2[q].y;
            W1ts[r1*136 + col]   = pq2[q].z;
            W1ts[r1*136 + col+1] = pq2[q].w;
        }
    }
    __syncthreads();
    // ---- act2 ----
    const int PR[6] = {0,0,2,0,1,2};
    const int QR[6] = {2,1,1,2,1,0};
    const int QS[6] = {0,0,0,1,1,1};
    for (int i = tid; i < 6144; i += 256) {
        int p = i >> 10, rem = i & 1023;
        int b = rem >> 6, k = rem & 63;
        float pv = W1ts[(PR[p]*16 + b)*136 + k];
        float qv = QS[p] ? PQ1s[(QR[p]*16 + b)*132 + 64 + k]
                         : W1ts[(QR[p]*16 + b)*136 + 64 + k];
        float tv = pv + qv + b1s[k];
        g_act2[((size_t)p*NB + bb0 + b)*64 + k] = tv > 0.f ? tv : 0.2f*tv;
    }
}

// -------------------------- k6: stage-2 second layer ------------------------
#define K6_SMEM ((2*128*68 + 64*68 + 768)*4)
__global__ __launch_bounds__(256) void k6_mma(const float* __restrict__ b2)
{
    extern __shared__ float sm6[];
    float* AsB   = sm6;
    float* W2ts  = sm6 + 2*128*68;
    float* wtriS = sm6 + 2*128*68 + 64*68;
    int tid = threadIdx.x;
    int b0 = blockIdx.x * 128, n0 = blockIdx.y * 64;

    for (int i = tid; i < 1024; i += 256) {
        int r = i >> 4, c4 = i & 15;
        cpasync16(&W2ts[r*68 + c4*4], &g_W2t[(size_t)(n0 + r)*64 + c4*4]);
    }
    {
        const float* Ap = g_act2 + ((size_t)0*NB + b0)*64;
        for (int i = tid; i < 2048; i += 256) {
            int r = i >> 4, c4 = i & 15;
            cpasync16(&AsB[r*68 + c4*4], &Ap[(size_t)r*64 + c4*4]);
        }
    }
    CP_COMMIT;
    for (int i = tid; i < 768; i += 256) wtriS[i] = g_wtri[(size_t)b0*6 + i];

    int lane = tid & 31, wid = tid >> 5;
    int t4 = lane & 3, g = lane >> 2;
    int wm = wid >> 1, wn = wid & 1;
    int rw = wm*32, cw = wn*32;

    unsigned w2tu = (unsigned)__cvta_generic_to_shared(W2ts);
    unsigned pB  = b_ptr(w2tu, cw, 68, lane);
    unsigned As0u = (unsigned)__cvta_generic_to_shared(AsB);

    float4 tri[2][4] = {};
#pragma unroll 1
    for (int p = 0; p < 6; p++) {
        if (p + 1 < 6) {
            const float* Ap = g_act2 + ((size_t)(p+1)*NB + b0)*64;
            float* Ad = AsB + ((p+1) & 1)*128*68;
            for (int i = tid; i < 2048; i += 256) {
                int r = i >> 4, c4 = i & 15;
                cpasync16(&Ad[r*68 + c4*4], &Ap[(size_t)r*64 + c4*4]);
            }
            CP_COMMIT;
            CP_WAIT1;
        } else {
            CP_WAIT0;
        }
        __syncthreads();
        unsigned Au = As0u + (unsigned)((p & 1)*128*68*4);
        unsigned pA0 = a_ptr(Au, rw, 68, lane);
        unsigned pA1 = pA0 + 16*68*4;
        float4 acc[2][4] = {};
#pragma unroll
        for (int ks = 0; ks < 8; ks++) {
            uint4 a0 = ldsm4(pA0 + ks*32);
            uint4 a1 = ldsm4(pA1 + ks*32);
            uint4 b0v = ldsm4(pB + ks*32);
            uint4 b1v= ldsm4(pB + 16*68*4 + ks*32);
            mma_t(acc[0][0], a0.x,a0.y,a0.z,a0.w, b0v.x, b0v.y);
            mma_t(acc[0][1], a0.x,a0.y,a0.z,a0.w, b0v.z, b0v.w);
            mma_t(acc[0][2], a0.x,a0.y,a0.z,a0.w, b1v.x, b1v.y);
            mma_t(acc[0][3], a0.x,a0.y,a0.z,a0.w, b1v.z, b1v.w);
            mma_t(acc[1][0], a1.x,a1.y,a1.z,a1.w, b0v.x, b0v.y);
            mma_t(acc[1][1], a1.x,a1.y,a1.z,a1.w, b0v.z, b0v.w);
            mma_t(acc[1][2], a1.x,a1.y,a1.z,a1.w, b1v.x, b1v.y);
            mma_t(acc[1][3], a1.x,a1.y,a1.z,a1.w, b1v.z, b1v.w);
        }
#pragma unroll
        for (int m = 0; m < 2; m++) {
            int lr0 = rw + m*16 + g;
            int lr1 = lr0 + 8;
            float wt0 = wtriS[lr0*6 + p];
            float wt1 = wtriS[lr1*6 + p];
#pragma unroll
            for (int q = 0; q < 4; q++) {
                int col = n0 + cw + q*8 + t4*2;
                float2 b2v = *(const float2*)&b2[col];
                float t;
                t = tanh_fast(acc[m][q].x + b2v.x)*wt0; tri[m][q].x += (t > 0.f ? t : 0.01f*t);
                t = tanh_fast(acc[m][q].y + b2v.y)*wt0; tri[m][q].y += (t > 0.f ? t : 0.01f*t);
                t = tanh_fast(acc[m][q].z + b2v.x)*wt1; tri[m][q].z += (t > 0.f ? t : 0.01f*t);
                t = tanh_fast(acc[m][q].w + b2v.y)*wt1; tri[m][q].w += (t > 0.f ? t : 0.01f*t);
            }
        }
        __syncthreads();
    }
#pragma unroll
    for (int m = 0; m < 2; m++) {
        size_t r0 = b0 + rw + m*16 + g, r1 = r0 + 8;
#pragma unroll
        for (int q = 0; q < 4; q++) {
            int col = n0 + cw + q*8 + t4*2;
            float2 o0; o0.x = tri[m][q].x; o0.y = tri[m][q].y;
            float2 o1; o1.x = tri[m][q].z; o1.y = tri[m][q].w;
            *(float2*)&g_tri[r0*1024 + col] = o0;
            *(float2*)&g_tri[r1*1024 + col] = o1;
        }
    }
}

// -------------------------- k7: fused head (tf32 layer1, K=64 chunks) -------
#define K7_SMEM ((4352 + 4608 + 3328 + 3328 + 512 + 3000)*4)
__global__ __launch_bounds__(256) void k7_final(
    const float* __restrict__ bnb,
    const float* __restrict__ l1b,
    const float* __restrict__ l2W, const float* __restrict__ l2b,
    const float* __restrict__ l3W, const float* __restrict__ l3b,
    float* __restrict__ out)
{
    extern __shared__ float pool[];
    float* As  = pool;
    float* Bs  = pool + 4352;
    float* Y1  = pool + 8960;
    float* Y2  = pool + 12288;
    float* Y3  = pool + 15616;
    float* W23 = pool + 16128;
    int tid = threadIdx.x;
    int b0 = blockIdx.x * 64;
    int lane = tid & 31, wid = tid >> 5;
    int g = lane >> 2, t4 = lane & 3;
    int wm = wid >> 2, wn = wid & 3;
    int rw = wm*32, cw = wn*16;

    for (int i = tid; i < 2500; i += 256) {
        int k = i / 50, c = i - k*50;
        W23[k*52 + c] = l2W[i];
    }
    for (int i = tid; i < 400; i += 256) W23[2600 + i] = l3W[i];

    float4 acc[2][2] = {};
    for (int t = 0; t < 48; t++) {
        int kk = t * 64;
        int region = kk >> 10;
        const float* src = region == 0 ? g_uni : (region == 1 ? g_bisum : g_tri);
        __syncthreads();
        for (int i = tid; i < 1024; i += 256) {
            int k = i >> 4, c4 = i & 15;
            cpasync16(&Bs[k*72 + c4*4], &g_l1Wp[(size_t)(kk + k)*64 + c4*4]);
        }
        CP_COMMIT;
        for (int i = tid; i < 1024; i += 256) {
            int r = i >> 4, c4 = i & 15;
            float4 v = *(const float4*)&src[(size_t)(b0 + r)*1024 + (kk & 1023) + c4*4];
            int j = kk + c4*4;
            float* d = &As[r*68 + c4*4];
            d[0] = f2tf_f(fmaf(v.x, g_bnsc[j],   bnb[j]));
            d[1] = f2tf_f(fmaf(v.y, g_bnsc[j+1], bnb[j+1]));
            d[2] = f2tf_f(fmaf(v.z, g_bnsc[j+2], bnb[j+2]));
            d[3] = f2tf_f(fmaf(v.w, g_bnsc[j+3], bnb[j+3]));
        }
        CP_WAIT0;
        __syncthreads();
#pragma unroll
        for (int ks = 0; ks < 8; ks++) {
            unsigned a[2][4], bf[2][2];
#pragma unroll
            for (int m = 0; m < 2; m++) {
                int r = rw + m*16 + g;
                a[m][0] = __float_as_uint(As[r*68 + ks*8 + t4]);
                a[m][1] = __float_as_uint(As[(r+8)*68 + ks*8 + t4]);
                a[m][2] = __float_as_uint(As[r*68 + ks*8 + t4 + 4]);
                a[m][3] = __float_as_uint(As[(r+8)*68 + ks*8 + t4 + 4]);
            }
#pragma unroll
            for (int n = 0; n < 2; n++) {
                int c = cw + n*8 + g;
                bf[n][0] = __float_as_uint(Bs[(ks*8 + t4)*72 + c]);
                bf[n][1] = __float_as_uint(Bs[(ks*8 + t4 + 4)*72 + c]);
            }
#pragma unroll
            for (int m = 0; m < 2; m++)
#pragma unroll
            for (int n = 0; n < 2; n++)
                mma_t(acc[m][n], a[m][0],a[m][1],a[m][2],a[m][3], bf[n][0], bf[n][1]);
        }
    }
    __syncthreads();
#pragma unroll
    for (int m = 0; m < 2; m++) {
        int r0 = rw + m*16 + g, r1 = r0 + 8;
#pragma unroll
        for (int n = 0; n < 2; n++) {
            int c = cw + n*8 + t4*2;
            if (c < 50)   { Y1[r0*52 + c]   = tanhf(acc[m][n].x + l1b[c]);
                            Y1[r1*52 + c]   = tanhf(acc[m][n].z + l1b[c]); }
            if (c+1 < 50) { Y1[r0*52 + c+1] = tanhf(acc[m][n].y + l1b[c+1]);
                            Y1[r1*52 + c+1] = tanhf(acc[m][n].w + l1b[c+1]); }
        }
    }
    __syncthreads();

    for (int o = tid; o < 3200; o += 256) {
        int r = o / 50, c = o - r*50;
        float a = l2b[c];
        for (int k = 0; k < 50; k++)
            a = fmaf(Y1[r*52 + k], W23[k*52 + c], a);
        Y2[r*52 + c] = tanhf(a);
    }
    __syncthreads();

    for (int o = tid; o < 512; o += 256) {
        int r = o >> 3, c = o & 7;
        float a = l3b[c];
        for (int k = 0; k < 50; k++)
            a = fmaf(Y2[r*52 + k], W23[2600 + k*8 + c], a);
        Y3[r*8 + c] = a;
    }
    __syncthreads();
    if (tid < 64) {
        int r = tid;
        float m = -1e30f;
#pragma unroll
        for (int c = 0; c < 8; c++) m = fmaxf(m, Y3[r*8 + c]);
        float e[8], s = 0.f;
#pragma unroll
        for (int c = 0; c < 8; c++) { e[c] = expf(Y3[r*8 + c] - m); s += e[c]; }
        float inv = 1.f / s;
        float* orow = out + (size_t)(b0 + r)*8;
#pragma unroll
        for (int c = 0; c < 8; c++) orow[c] = e[c]*inv;
    }
}

// -------------------------- launch ------------------------------------------
extern "C" void kernel_launch(void* const* d_in, const int* in_sizes, int n_in,
                              void* d_out, int out_size)
{
    const float* x    = (const float*)d_in[0];
    const float* attW = (const float*)d_in[1];
    const float* attb = (const float*)d_in[2];
    const float* gfW1 = (const float*)d_in[3];
    const float* gfb1 = (const float*)d_in[4];
    const float* gfW2 = (const float*)d_in[5];
    const float* gfb2 = (const float*)d_in[6];
    const float* bng  = (const float*)d_in[7];
    const float* bnb  = (const float*)d_in[8];
    const float* l1W  = (const float*)d_in[9];
    const float* l1b  = (const float*)d_in[10];
    const float* l2W  = (const float*)d_in[11];
    const float* l2b  = (const float*)d_in[12];
    const float* l3W  = (const float*)d_in[13];
    const float* l3b  = (const float*)d_in[14];
    float* out  = (float*)d_out;
    int wflag = (out_size >= NB*20) ? 1 : 0;
    float* outW = out + (size_t)NB*8;

    static int attr_done = 0;
    if (!attr_done) {
        cudaFuncSetAttribute(k_projA, cudaFuncAttributeMaxDynamicSharedMemorySize, KPA_SMEM);
        cudaFuncSetAttribute(kFuse,   cudaFuncAttributeMaxDynamicSharedMemorySize, KF_SMEM);
        cudaFuncSetAttribute(k6_mma,  cudaFuncAttributeMaxDynamicSharedMemorySize, K6_SMEM);
        cudaFuncSetAttribute(k7_final,cudaFuncAttributeMaxDynamicSharedMemorySize, K7_SMEM);
        attr_done = 1;
    }

    k0_prep<<<1549, 256>>>(gfW1, gfW2, l1W, bng);
    k_projA<<<NR3/96, 256, KPA_SMEM>>>(x, attW, attb, outW, wflag);
    kFuse<<<NB/16, 256, KF_SMEM>>>(x, gfb1, gfb2, outW, wflag);
    dim3 g6(NB/128, 16);
    k6_mma<<<g6, 256, K6_SMEM>>>(gfb2);
    k7_final<<<NB/64, 256, K7_SMEM>>>(bnb, l1b, l2W, l2b, l3W, l3b, out);
}